// round 7
// baseline (speedup 1.0000x reference)
#include <cuda_runtime.h>
#include <stdint.h>
#include <math.h>

#define TOK 4096
#define DM 1024
#define DFF 4096

// ---------------- scratch (static device globals; no allocs) ----------------
__device__ float g_xn[TOK * DM];           // LN output (tf32-rounded)
__device__ float g_q[TOK * DM];
__device__ float g_k[TOK * DM];
__device__ float g_v[TOK * DM];
__device__ float g_att[TOK * DM];
__device__ float g_h1[TOK * DM];           // H after attention residual (exact)
__device__ float g_mlp[(size_t)TOK * DFF]; // GELU hidden (tf32-rounded)
__device__ float g_wqkvo[4 * DM * DM];     // tf32-rounded weights
__device__ float g_w1r[(size_t)DM * DFF];
__device__ float g_w2r[(size_t)DFF * DM];

// ---------------- TF32 primitives ----------------
__device__ __forceinline__ uint32_t f2tf32(float x) {
    uint32_t r;
    asm("cvt.rna.tf32.f32 %0, %1;" : "=r"(r) : "f"(x));
    return r;
}
__device__ __forceinline__ float roundtf(float x) {
    return __uint_as_float(f2tf32(x));
}

__device__ __forceinline__ void mma_tf32(float c[4],
                                         uint32_t a0, uint32_t a1,
                                         uint32_t a2, uint32_t a3,
                                         uint32_t b0, uint32_t b1) {
    asm volatile(
        "mma.sync.aligned.m16n8k8.row.col.f32.tf32.tf32.f32 "
        "{%0,%1,%2,%3}, {%4,%5,%6,%7}, {%8,%9}, {%0,%1,%2,%3};\n"
        : "+f"(c[0]), "+f"(c[1]), "+f"(c[2]), "+f"(c[3])
        : "r"(a0), "r"(a1), "r"(a2), "r"(a3), "r"(b0), "r"(b1));
}

__device__ __forceinline__ void cp_async16(uint32_t smem, const void* gptr) {
    asm volatile("cp.async.cg.shared.global [%0], [%1], 16;\n"
                 :: "r"(smem), "l"(gptr));
}

// ---------------- fused tf32 rounding pass (all weights, one launch) --------
struct RoundArgs {
    const float4* src[6];
    float4*       dst[6];
    int           n4[6];
};

__global__ __launch_bounds__(256) void round_all(RoundArgs ra) {
    int seg = blockIdx.y;
    int i = blockIdx.x * 256 + threadIdx.x;
    if (i < ra.n4[seg]) {
        float4 v = ra.src[seg][i];
        v.x = roundtf(v.x); v.y = roundtf(v.y);
        v.z = roundtf(v.z); v.w = roundtf(v.w);
        ra.dst[seg][i] = v;
    }
}

// ---------------- LayerNorm: one block per row (tf32-rounded output) --------
__global__ __launch_bounds__(256) void ln_kernel(const float* __restrict__ x,
                                                 const float* __restrict__ g,
                                                 const float* __restrict__ b,
                                                 float* __restrict__ out) {
    int row = blockIdx.x;
    int t = threadIdx.x;
    const float4* xr = (const float4*)(x + (size_t)row * DM);
    float4 v = xr[t];
    float s  = v.x + v.y + v.z + v.w;
    float ss = v.x * v.x + v.y * v.y + v.z * v.z + v.w * v.w;
    #pragma unroll
    for (int o = 16; o > 0; o >>= 1) {
        s  += __shfl_xor_sync(0xffffffffu, s, o);
        ss += __shfl_xor_sync(0xffffffffu, ss, o);
    }
    __shared__ float red[2][8];
    if ((t & 31) == 0) { red[0][t >> 5] = s; red[1][t >> 5] = ss; }
    __syncthreads();
    float ts = 0.f, tss = 0.f;
    #pragma unroll
    for (int i = 0; i < 8; i++) { ts += red[0][i]; tss += red[1][i]; }
    float mu   = ts * (1.0f / DM);
    float var  = tss * (1.0f / DM) - mu * mu;
    float rstd = rsqrtf(var + 1e-5f);
    float4 gv = ((const float4*)g)[t];
    float4 bv = ((const float4*)b)[t];
    float4 o;
    o.x = roundtf((v.x - mu) * rstd * gv.x + bv.x);
    o.y = roundtf((v.y - mu) * rstd * gv.y + bv.y);
    o.z = roundtf((v.z - mu) * rstd * gv.z + bv.z);
    o.w = roundtf((v.w - mu) * rstd * gv.w + bv.w);
    ((float4*)(out + (size_t)row * DM))[t] = o;
}

// ---------------- TF32 tensor-core GEMM body ----------------
// C[M,N] = A[M,K] @ B[K,N] (+ epilogue). A and B MUST be tf32-pre-rounded.
// EPI: 0 = none, 1 = +bias then exact GELU, 2 = +bias +res, 3 = +res
// RND: round stored C to tf32 (for outputs consumed as mma operands)
// Block tile 128x128x32, 8 warps as 2(m) x 4(n); per warp 4x4 m16n8k8 tiles.

#define ASTR 36
#define BSTR 136
#define ASZ (128 * ASTR)
#define BSZ (32 * BSTR)
#define GEMM_SMEM ((ASZ + BSZ) * 2 * sizeof(float))

template <int EPI, int RND>
__device__ __forceinline__ void gemm_body(const float* __restrict__ A,
                                          const float* __restrict__ B,
                                          const float* __restrict__ bias,
                                          const float* __restrict__ res,
                                          float* __restrict__ C,
                                          int M, int N, int K, float* sm) {
    uint32_t sbase = (uint32_t)__cvta_generic_to_shared(sm);

    int t = threadIdx.x;
    int bn = blockIdx.x, bm = blockIdx.y;
    int wid = t >> 5, lane = t & 31;
    int wm = wid & 1, wn = wid >> 1;          // 2 x 4 warp grid
    int g = lane >> 2, tig = lane & 3;

    const float* Abase = A + (size_t)(bm * 128) * K;
    const float* Bbase = B + bn * 128;

    auto load_tiles = [&](int k0, int buf) {
        uint32_t sa = sbase + (uint32_t)(buf * (ASZ + BSZ)) * 4u;
        uint32_t sb = sa + (uint32_t)ASZ * 4u;
        const float* Ap = Abase + k0;
        const float* Bp = Bbase + (size_t)k0 * N;
        #pragma unroll
        for (int i = 0; i < 4; i++) {          // A: 128 rows x 32 cols
            int idx = t + i * 256;
            int r = idx >> 3, c4 = (idx & 7) << 2;
            cp_async16(sa + (uint32_t)(r * ASTR + c4) * 4u,
                       Ap + (size_t)r * K + c4);
        }
        #pragma unroll
        for (int i = 0; i < 4; i++) {          // B: 32 rows x 128 cols
            int idx = t + i * 256;
            int r = idx >> 5, c4 = (idx & 31) << 2;
            cp_async16(sb + (uint32_t)(r * BSTR + c4) * 4u,
                       Bp + (size_t)r * N + c4);
        }
        asm volatile("cp.async.commit_group;\n");
    };

    float acc[4][4][4];
    #pragma unroll
    for (int i = 0; i < 4; i++)
        #pragma unroll
        for (int j = 0; j < 4; j++)
            #pragma unroll
            for (int r = 0; r < 4; r++) acc[i][j][r] = 0.f;

    load_tiles(0, 0);
    int NC = K >> 5;
    for (int c = 0; c < NC; c++) {
        asm volatile("cp.async.wait_group 0;\n");
        __syncthreads();
        if (c + 1 < NC) load_tiles((c + 1) << 5, (c + 1) & 1);

        const float* a = sm + (c & 1) * (ASZ + BSZ);
        const float* b = a + ASZ;

        #pragma unroll
        for (int ks = 0; ks < 4; ks++) {
            int kc = ks * 8;
            uint32_t af[4][4], bf[4][2];
            #pragma unroll
            for (int mt = 0; mt < 4; mt++) {
                int r = wm * 64 + mt * 16 + g;
                af[mt][0] = __float_as_uint(a[r * ASTR + kc + tig]);
                af[mt][1] = __float_as_uint(a[(r + 8) * ASTR + kc + tig]);
                af[mt][2] = __float_as_uint(a[r * ASTR + kc + tig + 4]);
                af[mt][3] = __float_as_uint(a[(r + 8) * ASTR + kc + tig + 4]);
            }
            #pragma unroll
            for (int nt = 0; nt < 4; nt++) {
                int cn = wn * 32 + nt * 8 + g;
                bf[nt][0] = __float_as_uint(b[(kc + tig) * BSTR + cn]);
                bf[nt][1] = __float_as_uint(b[(kc + tig + 4) * BSTR + cn]);
            }
            #pragma unroll
            for (int mt = 0; mt < 4; mt++)
                #pragma unroll
                for (int nt = 0; nt < 4; nt++)
                    mma_tf32(acc[mt][nt], af[mt][0], af[mt][1], af[mt][2],
                             af[mt][3], bf[nt][0], bf[nt][1]);
        }
        __syncthreads();
    }

    int row0 = bm * 128 + wm * 64;
    int col0 = bn * 128 + wn * 32;
    #pragma unroll
    for (int mt = 0; mt < 4; mt++) {
        #pragma unroll
        for (int half = 0; half < 2; half++) {
            int r = row0 + mt * 16 + half * 8 + g;
            size_t rb = (size_t)r * N;
            #pragma unroll
            for (int nt = 0; nt < 4; nt++) {
                int cn = col0 + nt * 8 + tig * 2;
                float x0 = acc[mt][nt][half * 2];
                float x1 = acc[mt][nt][half * 2 + 1];
                if (EPI == 1) {
                    x0 += bias[cn];
                    x1 += bias[cn + 1];
                    x0 = 0.5f * x0 * (1.0f + erff(x0 * 0.70710678118654752f));
                    x1 = 0.5f * x1 * (1.0f + erff(x1 * 0.70710678118654752f));
                } else if (EPI == 2) {
                    x0 += bias[cn] + res[rb + cn];
                    x1 += bias[cn + 1] + res[rb + cn + 1];
                } else if (EPI == 3) {
                    x0 += res[rb + cn];
                    x1 += res[rb + cn + 1];
                }
                if (RND) { x0 = roundtf(x0); x1 = roundtf(x1); }
                *(float2*)(C + rb + cn) = make_float2(x0, x1);
            }
        }
    }
}

template <int EPI, int RND>
__global__ __launch_bounds__(256, 2) void gemm_tf32(const float* __restrict__ A,
                                                    const float* __restrict__ B,
                                                    const float* __restrict__ bias,
                                                    const float* __restrict__ res,
                                                    float* __restrict__ C,
                                                    int M, int N, int K) {
    extern __shared__ float sm[];
    gemm_body<EPI, RND>(A, B, bias, res, C, M, N, K, sm);
}

// Fused Q/K/V projection: blockIdx.z selects weight + destination.
__global__ __launch_bounds__(256, 2) void gemm_qkv(const float* __restrict__ A,
                                                   const float* __restrict__ W,
                                                   float* __restrict__ q,
                                                   float* __restrict__ k,
                                                   float* __restrict__ v,
                                                   int M, int N, int K) {
    extern __shared__ float sm[];
    const float* B = W + (size_t)blockIdx.z * DM * DM;
    float* C = (blockIdx.z == 0) ? q : (blockIdx.z == 1) ? k : v;
    gemm_body<0, 1>(A, B, nullptr, nullptr, C, M, N, K, sm);
}

// ---------------- TF32 tensor-core causal flash attention ----------------
// Q,K,V pre-rounded to tf32; P fed raw (<=1 ulp_tf32 effect). Output rounded.
#define ATSTR 68
#define ATTN_SMEM (3 * 64 * ATSTR * 4)

__global__ __launch_bounds__(128) void attn_tc(const float* __restrict__ Q,
                                               const float* __restrict__ K,
                                               const float* __restrict__ V,
                                               float* __restrict__ O) {
    extern __shared__ float sm[];
    float* sK  = sm;
    float* sVt = sm + 64 * ATSTR;
    float* sP  = sm + 2 * 64 * ATSTR;   // Q staging, then P staging

    int qb = blockIdx.x, h = blockIdx.y, bb = blockIdx.z;
    int t = threadIdx.x;
    int w = t >> 5, lane = t & 31;
    int g = lane >> 2, tig = lane & 3;
    int row = w * 16 + g;               // local q row (also handles row+8)
    size_t base = ((size_t)bb * 2048) * DM + (size_t)h * 64;

    // stage Q tile -> sP
    #pragma unroll
    for (int i = 0; i < 8; i++) {
        int idx = t + i * 128;
        int r = idx >> 4, c4 = (idx & 15) << 2;
        *(float4*)&sP[r * ATSTR + c4] =
            *(const float4*)(Q + base + (size_t)(qb * 64 + r) * DM + c4);
    }
    __syncthreads();

    // extract Q fragments (held in registers for the whole kernel)
    uint32_t qf[8][4];
    #pragma unroll
    for (int ks = 0; ks < 8; ks++) {
        int kc = ks * 8;
        qf[ks][0] = __float_as_uint(sP[row * ATSTR + kc + tig]);
        qf[ks][1] = __float_as_uint(sP[(row + 8) * ATSTR + kc + tig]);
        qf[ks][2] = __float_as_uint(sP[row * ATSTR + kc + tig + 4]);
        qf[ks][3] = __float_as_uint(sP[(row + 8) * ATSTR + kc + tig + 4]);
    }

    float oa[8][4];
    #pragma unroll
    for (int nt = 0; nt < 8; nt++)
        #pragma unroll
        for (int r = 0; r < 4; r++) oa[nt][r] = 0.f;
    float m0 = -1e30f, m1 = -1e30f, l0 = 0.f, l1 = 0.f;

    for (int kb = 0; kb <= qb; kb++) {
        __syncthreads();  // prior PV reads of sVt done; Q extraction done (kb==0)
        #pragma unroll
        for (int i = 0; i < 8; i++) {
            int idx = t + i * 128;
            int r = idx >> 4, c4 = (idx & 15) << 2;
            size_t goff = base + (size_t)(kb * 64 + r) * DM + c4;
            *(float4*)&sK[r * ATSTR + c4] = *(const float4*)(K + goff);
            float4 vv = *(const float4*)(V + goff);
            sVt[(c4 + 0) * ATSTR + r] = vv.x;
            sVt[(c4 + 1) * ATSTR + r] = vv.y;
            sVt[(c4 + 2) * ATSTR + r] = vv.z;
            sVt[(c4 + 3) * ATSTR + r] = vv.w;
        }
        __syncthreads();

        // S = Q K^T
        float s[8][4];
        #pragma unroll
        for (int nt = 0; nt < 8; nt++)
            #pragma unroll
            for (int r = 0; r < 4; r++) s[nt][r] = 0.f;
        #pragma unroll
        for (int ks = 0; ks < 8; ks++) {
            int kc = ks * 8;
            #pragma unroll
            for (int nt = 0; nt < 8; nt++) {
                int cn = nt * 8 + g;
                uint32_t b0 = __float_as_uint(sK[cn * ATSTR + kc + tig]);
                uint32_t b1 = __float_as_uint(sK[cn * ATSTR + kc + tig + 4]);
                mma_tf32(s[nt], qf[ks][0], qf[ks][1], qf[ks][2], qf[ks][3],
                         b0, b1);
            }
        }
        #pragma unroll
        for (int nt = 0; nt < 8; nt++)
            #pragma unroll
            for (int r = 0; r < 4; r++) s[nt][r] *= 0.125f;
        if (kb == qb) {
            int q0 = row, q1 = row + 8;
            #pragma unroll
            for (int nt = 0; nt < 8; nt++) {
                int c0 = nt * 8 + 2 * tig, c1 = c0 + 1;
                if (c0 > q0) s[nt][0] = -1e30f;
                if (c1 > q0) s[nt][1] = -1e30f;
                if (c0 > q1) s[nt][2] = -1e30f;
                if (c1 > q1) s[nt][3] = -1e30f;
            }
        }

        // online softmax
        float mt0 = -1e30f, mt1 = -1e30f;
        #pragma unroll
        for (int nt = 0; nt < 8; nt++) {
            mt0 = fmaxf(mt0, fmaxf(s[nt][0], s[nt][1]));
            mt1 = fmaxf(mt1, fmaxf(s[nt][2], s[nt][3]));
        }
        #pragma unroll
        for (int o = 1; o <= 2; o <<= 1) {
            mt0 = fmaxf(mt0, __shfl_xor_sync(0xffffffffu, mt0, o));
            mt1 = fmaxf(mt1, __shfl_xor_sync(0xffffffffu, mt1, o));
        }
        float mn0 = fmaxf(m0, mt0), mn1 = fmaxf(m1, mt1);
        float corr0 = __expf(m0 - mn0), corr1 = __expf(m1 - mn1);
        m0 = mn0; m1 = mn1;
        float rs0 = 0.f, rs1 = 0.f;
        #pragma unroll
        for (int nt = 0; nt < 8; nt++) {
            s[nt][0] = __expf(s[nt][0] - mn0);
            s[nt][1] = __expf(s[nt][1] - mn0);
            s[nt][2] = __expf(s[nt][2] - mn1);
            s[nt][3] = __expf(s[nt][3] - mn1);
            rs0 += s[nt][0] + s[nt][1];
            rs1 += s[nt][2] + s[nt][3];
        }
        #pragma unroll
        for (int o = 1; o <= 2; o <<= 1) {
            rs0 += __shfl_xor_sync(0xffffffffu, rs0, o);
            rs1 += __shfl_xor_sync(0xffffffffu, rs1, o);
        }
        l0 = l0 * corr0 + rs0;
        l1 = l1 * corr1 + rs1;
        #pragma unroll
        for (int nt = 0; nt < 8; nt++) {
            oa[nt][0] *= corr0; oa[nt][1] *= corr0;
            oa[nt][2] *= corr1; oa[nt][3] *= corr1;
        }

        // stage P (each warp writes/reads only its own 16 rows)
        #pragma unroll
        for (int nt = 0; nt < 8; nt++) {
            int cc = nt * 8 + 2 * tig;
            *(float2*)&sP[row * ATSTR + cc]       = make_float2(s[nt][0], s[nt][1]);
            *(float2*)&sP[(row + 8) * ATSTR + cc] = make_float2(s[nt][2], s[nt][3]);
        }
        __syncwarp();

        // O += P @ V
        #pragma unroll
        for (int ks = 0; ks < 8; ks++) {
            int kc = ks * 8;
            uint32_t a0 = __float_as_uint(sP[row * ATSTR + kc + tig]);
            uint32_t a1 = __float_as_uint(sP[(row + 8) * ATSTR + kc + tig]);
            uint32_t a2 = __float_as_uint(sP[row * ATSTR + kc + tig + 4]);
            uint32_t a3 = __float_as_uint(sP[(row + 8) * ATSTR + kc + tig + 4]);
            #pragma unroll
            for (int nt = 0; nt < 8; nt++) {
                int cn = nt * 8 + g;
                uint32_t b0 = __float_as_uint(sVt[cn * ATSTR + kc + tig]);
                uint32_t b1 = __float_as_uint(sVt[cn * ATSTR + kc + tig + 4]);
                mma_tf32(oa[nt], a0, a1, a2, a3, b0, b1);
            }
        }
        __syncwarp();   // P reads complete before next-tile reuse
    }

    // epilogue (rounded: att feeds the Wo GEMM as an mma operand)
    float inv0 = 1.0f / l0, inv1 = 1.0f / l1;
    size_t r0 = base + (size_t)(qb * 64 + row) * DM;
    size_t r1 = base + (size_t)(qb * 64 + row + 8) * DM;
    #pragma unroll
    for (int nt = 0; nt < 8; nt++) {
        int cc = nt * 8 + 2 * tig;
        *(float2*)(O + r0 + cc) = make_float2(roundtf(oa[nt][0] * inv0),
                                              roundtf(oa[nt][1] * inv0));
        *(float2*)(O + r1 + cc) = make_float2(roundtf(oa[nt][2] * inv1),
                                              roundtf(oa[nt][3] * inv1));
    }
}

// ---------------- launch ----------------
extern "C" void kernel_launch(void* const* d_in, const int* in_sizes, int n_in,
                              void* d_out, int out_size) {
    const float* H    = (const float*)d_in[0];
    const float* Wq   = (const float*)d_in[1];
    const float* Wk   = (const float*)d_in[2];
    const float* Wv   = (const float*)d_in[3];
    const float* Wo   = (const float*)d_in[4];
    const float* ln1g = (const float*)d_in[5];
    const float* ln1b = (const float*)d_in[6];
    const float* ln2g = (const float*)d_in[7];
    const float* ln2b = (const float*)d_in[8];
    const float* W1   = (const float*)d_in[9];
    const float* b1   = (const float*)d_in[10];
    const float* W2   = (const float*)d_in[11];
    const float* b2   = (const float*)d_in[12];
    float* out = (float*)d_out;

    float *xn, *q, *k, *v, *att, *h1, *mlp, *wqkvo, *w1r, *w2r;
    cudaGetSymbolAddress((void**)&xn,    g_xn);
    cudaGetSymbolAddress((void**)&q,     g_q);
    cudaGetSymbolAddress((void**)&k,     g_k);
    cudaGetSymbolAddress((void**)&v,     g_v);
    cudaGetSymbolAddress((void**)&att,   g_att);
    cudaGetSymbolAddress((void**)&h1,    g_h1);
    cudaGetSymbolAddress((void**)&mlp,   g_mlp);
    cudaGetSymbolAddress((void**)&wqkvo, g_wqkvo);
    cudaGetSymbolAddress((void**)&w1r,   g_w1r);
    cudaGetSymbolAddress((void**)&w2r,   g_w2r);

    cudaFuncSetAttribute(attn_tc, cudaFuncAttributeMaxDynamicSharedMemorySize,
                         ATTN_SMEM);
    cudaFuncSetAttribute(gemm_qkv, cudaFuncAttributeMaxDynamicSharedMemorySize,
                         (int)GEMM_SMEM);
    cudaFuncSetAttribute(gemm_tf32<1, 1>, cudaFuncAttributeMaxDynamicSharedMemorySize,
                         (int)GEMM_SMEM);
    cudaFuncSetAttribute(gemm_tf32<2, 0>, cudaFuncAttributeMaxDynamicSharedMemorySize,
                         (int)GEMM_SMEM);
    cudaFuncSetAttribute(gemm_tf32<3, 0>, cudaFuncAttributeMaxDynamicSharedMemorySize,
                         (int)GEMM_SMEM);

    dim3 gProj(DM / 128, TOK / 128);        // 8 x 32
    dim3 gQkv(DM / 128, TOK / 128, 3);      // 8 x 32 x 3
    dim3 gMlp1(DFF / 128, TOK / 128);       // 32 x 32

    // pre-round all weights to tf32 (single fused launch; graph-captured)
    int n4p = DM * DM / 4;                  // 262144
    int n4f = DM * DFF / 4;                 // 1048576
    RoundArgs ra;
    ra.src[0] = (const float4*)Wq; ra.dst[0] = (float4*)wqkvo;                 ra.n4[0] = n4p;
    ra.src[1] = (const float4*)Wk; ra.dst[1] = (float4*)(wqkvo + DM * DM);     ra.n4[1] = n4p;
    ra.src[2] = (const float4*)Wv; ra.dst[2] = (float4*)(wqkvo + 2 * DM * DM); ra.n4[2] = n4p;
    ra.src[3] = (const float4*)Wo; ra.dst[3] = (float4*)(wqkvo + 3 * DM * DM); ra.n4[3] = n4p;
    ra.src[4] = (const float4*)W1; ra.dst[4] = (float4*)w1r;                   ra.n4[4] = n4f;
    ra.src[5] = (const float4*)W2; ra.dst[5] = (float4*)w2r;                   ra.n4[5] = n4f;
    round_all<<<dim3((n4f + 255) / 256, 6), 256>>>(ra);

    // LN1
    ln_kernel<<<TOK, 256>>>(H, ln1g, ln1b, xn);
    // fused Q, K, V projections
    gemm_qkv<<<gQkv, 256, GEMM_SMEM>>>(xn, wqkvo, q, k, v, TOK, DM, DM);
    // fused causal attention (tensor cores)
    attn_tc<<<dim3(32, 16, 2), 128, ATTN_SMEM>>>(q, k, v, att);
    // O projection + residual (exact fp32 residual stream)
    gemm_tf32<3, 0><<<gProj, 256, GEMM_SMEM>>>(att, wqkvo + 3 * DM * DM, nullptr, H,
                                               h1, TOK, DM, DM);
    // LN2
    ln_kernel<<<TOK, 256>>>(h1, ln2g, ln2b, xn);
    // MLP
    gemm_tf32<1, 1><<<gMlp1, 256, GEMM_SMEM>>>(xn, w1r, b1, nullptr, mlp, TOK, DFF, DM);
    gemm_tf32<2, 0><<<gProj, 256, GEMM_SMEM>>>(mlp, w2r, b2, h1, out, TOK, DM, DFF);
}

// round 8
// speedup vs baseline: 1.0699x; 1.0699x over previous
#include <cuda_runtime.h>
#include <stdint.h>
#include <math.h>

#define TOK 4096
#define DM 1024
#define DFF 4096

// ---------------- scratch (static device globals; no allocs) ----------------
__device__ float g_xn[TOK * DM];           // LN output (tf32-rounded)
__device__ float g_q[TOK * DM];
__device__ float g_k[TOK * DM];
__device__ float g_v[TOK * DM];
__device__ float g_att[TOK * DM];
__device__ float g_h1[TOK * DM];           // H after attention residual (exact)
__device__ float g_mlp[(size_t)TOK * DFF]; // GELU hidden (tf32-rounded)
__device__ float g_wqkvo[4 * DM * DM];     // tf32-rounded weights
__device__ float g_w1r[(size_t)DM * DFF];
__device__ float g_w2r[(size_t)DFF * DM];

// ---------------- TF32 primitives ----------------
__device__ __forceinline__ uint32_t f2tf32(float x) {
    uint32_t r;
    asm("cvt.rna.tf32.f32 %0, %1;" : "=r"(r) : "f"(x));
    return r;
}
__device__ __forceinline__ float roundtf(float x) {
    return __uint_as_float(f2tf32(x));
}

__device__ __forceinline__ void mma_tf32(float c[4],
                                         uint32_t a0, uint32_t a1,
                                         uint32_t a2, uint32_t a3,
                                         uint32_t b0, uint32_t b1) {
    asm volatile(
        "mma.sync.aligned.m16n8k8.row.col.f32.tf32.tf32.f32 "
        "{%0,%1,%2,%3}, {%4,%5,%6,%7}, {%8,%9}, {%0,%1,%2,%3};\n"
        : "+f"(c[0]), "+f"(c[1]), "+f"(c[2]), "+f"(c[3])
        : "r"(a0), "r"(a1), "r"(a2), "r"(a3), "r"(b0), "r"(b1));
}

__device__ __forceinline__ void cp_async16(uint32_t smem, const void* gptr) {
    asm volatile("cp.async.cg.shared.global [%0], [%1], 16;\n"
                 :: "r"(smem), "l"(gptr));
}

// ---------------- fused tf32 rounding pass (all weights, one launch) --------
struct RoundArgs {
    const float4* src[6];
    float4*       dst[6];
    int           n4[6];
};

__global__ __launch_bounds__(256) void round_all(RoundArgs ra) {
    int seg = blockIdx.y;
    int i = blockIdx.x * 256 + threadIdx.x;
    if (i < ra.n4[seg]) {
        float4 v = ra.src[seg][i];
        v.x = roundtf(v.x); v.y = roundtf(v.y);
        v.z = roundtf(v.z); v.w = roundtf(v.w);
        ra.dst[seg][i] = v;
    }
}

// ---------------- LayerNorm: one block per row (tf32-rounded output) --------
__global__ __launch_bounds__(256) void ln_kernel(const float* __restrict__ x,
                                                 const float* __restrict__ g,
                                                 const float* __restrict__ b,
                                                 float* __restrict__ out) {
    int row = blockIdx.x;
    int t = threadIdx.x;
    const float4* xr = (const float4*)(x + (size_t)row * DM);
    float4 v = xr[t];
    float s  = v.x + v.y + v.z + v.w;
    float ss = v.x * v.x + v.y * v.y + v.z * v.z + v.w * v.w;
    #pragma unroll
    for (int o = 16; o > 0; o >>= 1) {
        s  += __shfl_xor_sync(0xffffffffu, s, o);
        ss += __shfl_xor_sync(0xffffffffu, ss, o);
    }
    __shared__ float red[2][8];
    if ((t & 31) == 0) { red[0][t >> 5] = s; red[1][t >> 5] = ss; }
    __syncthreads();
    float ts = 0.f, tss = 0.f;
    #pragma unroll
    for (int i = 0; i < 8; i++) { ts += red[0][i]; tss += red[1][i]; }
    float mu   = ts * (1.0f / DM);
    float var  = tss * (1.0f / DM) - mu * mu;
    float rstd = rsqrtf(var + 1e-5f);
    float4 gv = ((const float4*)g)[t];
    float4 bv = ((const float4*)b)[t];
    float4 o;
    o.x = roundtf((v.x - mu) * rstd * gv.x + bv.x);
    o.y = roundtf((v.y - mu) * rstd * gv.y + bv.y);
    o.z = roundtf((v.z - mu) * rstd * gv.z + bv.z);
    o.w = roundtf((v.w - mu) * rstd * gv.w + bv.w);
    ((float4*)(out + (size_t)row * DM))[t] = o;
}

// ---------------- TF32 tensor-core GEMM body ----------------
// C[M,N] = A[M,K] @ B[K,N] (+ epilogue). A and B MUST be tf32-pre-rounded.
// EPI: 0 = none, 1 = +bias then exact GELU, 2 = +bias +res, 3 = +res
// RND: round stored C to tf32 (for outputs consumed as mma operands)
// Block tile 128x128x32, 8 warps as 2(m) x 4(n); per warp 4x4 m16n8k8 tiles.

#define ASTR 36
#define BSTR 136
#define ASZ (128 * ASTR)
#define BSZ (32 * BSTR)
#define GEMM_SMEM ((ASZ + BSZ) * 2 * sizeof(float))

template <int EPI, int RND>
__device__ __forceinline__ void gemm_body(const float* __restrict__ A,
                                          const float* __restrict__ B,
                                          const float* __restrict__ bias,
                                          const float* __restrict__ res,
                                          float* __restrict__ C,
                                          int M, int N, int K, float* sm) {
    uint32_t sbase = (uint32_t)__cvta_generic_to_shared(sm);

    int t = threadIdx.x;
    int bn = blockIdx.x, bm = blockIdx.y;
    int wid = t >> 5, lane = t & 31;
    int wm = wid & 1, wn = wid >> 1;          // 2 x 4 warp grid
    int g = lane >> 2, tig = lane & 3;

    const float* Abase = A + (size_t)(bm * 128) * K;
    const float* Bbase = B + bn * 128;

    auto load_tiles = [&](int k0, int buf) {
        uint32_t sa = sbase + (uint32_t)(buf * (ASZ + BSZ)) * 4u;
        uint32_t sb = sa + (uint32_t)ASZ * 4u;
        const float* Ap = Abase + k0;
        const float* Bp = Bbase + (size_t)k0 * N;
        #pragma unroll
        for (int i = 0; i < 4; i++) {          // A: 128 rows x 32 cols
            int idx = t + i * 256;
            int r = idx >> 3, c4 = (idx & 7) << 2;
            cp_async16(sa + (uint32_t)(r * ASTR + c4) * 4u,
                       Ap + (size_t)r * K + c4);
        }
        #pragma unroll
        for (int i = 0; i < 4; i++) {          // B: 32 rows x 128 cols
            int idx = t + i * 256;
            int r = idx >> 5, c4 = (idx & 31) << 2;
            cp_async16(sb + (uint32_t)(r * BSTR + c4) * 4u,
                       Bp + (size_t)r * N + c4);
        }
        asm volatile("cp.async.commit_group;\n");
    };

    float acc[4][4][4];
    #pragma unroll
    for (int i = 0; i < 4; i++)
        #pragma unroll
        for (int j = 0; j < 4; j++)
            #pragma unroll
            for (int r = 0; r < 4; r++) acc[i][j][r] = 0.f;

    load_tiles(0, 0);
    int NC = K >> 5;
    for (int c = 0; c < NC; c++) {
        asm volatile("cp.async.wait_group 0;\n");
        __syncthreads();
        if (c + 1 < NC) load_tiles((c + 1) << 5, (c + 1) & 1);

        const float* a = sm + (c & 1) * (ASZ + BSZ);
        const float* b = a + ASZ;

        #pragma unroll
        for (int ks = 0; ks < 4; ks++) {
            int kc = ks * 8;
            uint32_t af[4][4], bf[4][2];
            #pragma unroll
            for (int mt = 0; mt < 4; mt++) {
                int r = wm * 64 + mt * 16 + g;
                af[mt][0] = __float_as_uint(a[r * ASTR + kc + tig]);
                af[mt][1] = __float_as_uint(a[(r + 8) * ASTR + kc + tig]);
                af[mt][2] = __float_as_uint(a[r * ASTR + kc + tig + 4]);
                af[mt][3] = __float_as_uint(a[(r + 8) * ASTR + kc + tig + 4]);
            }
            #pragma unroll
            for (int nt = 0; nt < 4; nt++) {
                int cn = wn * 32 + nt * 8 + g;
                bf[nt][0] = __float_as_uint(b[(kc + tig) * BSTR + cn]);
                bf[nt][1] = __float_as_uint(b[(kc + tig + 4) * BSTR + cn]);
            }
            #pragma unroll
            for (int mt = 0; mt < 4; mt++)
                #pragma unroll
                for (int nt = 0; nt < 4; nt++)
                    mma_tf32(acc[mt][nt], af[mt][0], af[mt][1], af[mt][2],
                             af[mt][3], bf[nt][0], bf[nt][1]);
        }
        __syncthreads();
    }

    int row0 = bm * 128 + wm * 64;
    int col0 = bn * 128 + wn * 32;
    #pragma unroll
    for (int mt = 0; mt < 4; mt++) {
        #pragma unroll
        for (int half = 0; half < 2; half++) {
            int r = row0 + mt * 16 + half * 8 + g;
            size_t rb = (size_t)r * N;
            #pragma unroll
            for (int nt = 0; nt < 4; nt++) {
                int cn = col0 + nt * 8 + tig * 2;
                float x0 = acc[mt][nt][half * 2];
                float x1 = acc[mt][nt][half * 2 + 1];
                if (EPI == 1) {
                    x0 += bias[cn];
                    x1 += bias[cn + 1];
                    x0 = 0.5f * x0 * (1.0f + erff(x0 * 0.70710678118654752f));
                    x1 = 0.5f * x1 * (1.0f + erff(x1 * 0.70710678118654752f));
                } else if (EPI == 2) {
                    x0 += bias[cn] + res[rb + cn];
                    x1 += bias[cn + 1] + res[rb + cn + 1];
                } else if (EPI == 3) {
                    x0 += res[rb + cn];
                    x1 += res[rb + cn + 1];
                }
                if (RND) { x0 = roundtf(x0); x1 = roundtf(x1); }
                *(float2*)(C + rb + cn) = make_float2(x0, x1);
            }
        }
    }
}

template <int EPI, int RND>
__global__ __launch_bounds__(256) void gemm_tf32(const float* __restrict__ A,
                                                 const float* __restrict__ B,
                                                 const float* __restrict__ bias,
                                                 const float* __restrict__ res,
                                                 float* __restrict__ C,
                                                 int M, int N, int K) {
    extern __shared__ float sm[];
    gemm_body<EPI, RND>(A, B, bias, res, C, M, N, K, sm);
}

// Fused Q/K/V projection: blockIdx.z selects weight + destination.
__global__ __launch_bounds__(256) void gemm_qkv(const float* __restrict__ A,
                                                const float* __restrict__ W,
                                                float* __restrict__ q,
                                                float* __restrict__ k,
                                                float* __restrict__ v,
                                                int M, int N, int K) {
    extern __shared__ float sm[];
    const float* B = W + (size_t)blockIdx.z * DM * DM;
    float* C = (blockIdx.z == 0) ? q : (blockIdx.z == 1) ? k : v;
    gemm_body<0, 1>(A, B, nullptr, nullptr, C, M, N, K, sm);
}

// ---------------- TF32 tensor-core causal flash attention ----------------
// Q,K,V pre-rounded to tf32. V kept ROW-MAJOR (stride 72: conflict-free for
// the row.col B-fragment pattern) — no transpose needed. V double-buffered +
// K single-buffered via cp.async: K(kb+1)/V(kb+1) loads overlap softmax+PV.
#define KSTR 68
#define VSTR 72
#define PSTR 68
#define ATTN_SMEM ((64 * KSTR + 2 * 64 * VSTR + 64 * PSTR) * 4)

__global__ __launch_bounds__(128) void attn_tc(const float* __restrict__ Q,
                                               const float* __restrict__ K,
                                               const float* __restrict__ V,
                                               float* __restrict__ O) {
    extern __shared__ float sm[];
    float* sK  = sm;                         // [64][KSTR]
    float* sV0 = sm + 64 * KSTR;             // [64][VSTR]
    float* sV1 = sV0 + 64 * VSTR;            // [64][VSTR]
    float* sP  = sV1 + 64 * VSTR;            // Q staging, then per-warp P
    uint32_t sbase = (uint32_t)__cvta_generic_to_shared(sm);
    uint32_t aK  = sbase;
    uint32_t aV0 = sbase + (uint32_t)(64 * KSTR) * 4u;
    uint32_t aV1 = aV0 + (uint32_t)(64 * VSTR) * 4u;
    uint32_t aP  = aV1 + (uint32_t)(64 * VSTR) * 4u;

    int qb = gridDim.x - 1 - blockIdx.x;     // big tiles first
    int h = blockIdx.y, bb = blockIdx.z;
    int t = threadIdx.x;
    int w = t >> 5, lane = t & 31;
    int g = lane >> 2, tig = lane & 3;
    int row = w * 16 + g;                    // local q row (also row+8)
    size_t base = ((size_t)bb * 2048) * DM + (size_t)h * 64;

    // prologue: async-load Q -> sP, K(0) -> sK, V(0) -> sV0
    #pragma unroll
    for (int i = 0; i < 8; i++) {
        int idx = t + i * 128;
        int r = idx >> 4, c4 = (idx & 15) << 2;
        cp_async16(aP + (uint32_t)(r * PSTR + c4) * 4u,
                   Q + base + (size_t)(qb * 64 + r) * DM + c4);
        size_t goff = base + (size_t)r * DM + c4;
        cp_async16(aK + (uint32_t)(r * KSTR + c4) * 4u, K + goff);
        cp_async16(aV0 + (uint32_t)(r * VSTR + c4) * 4u, V + goff);
    }
    asm volatile("cp.async.commit_group;\n");
    asm volatile("cp.async.wait_group 0;\n");
    __syncthreads();

    // extract Q fragments (registers for the whole kernel)
    uint32_t qf[8][4];
    #pragma unroll
    for (int ks = 0; ks < 8; ks++) {
        int kc = ks * 8;
        qf[ks][0] = __float_as_uint(sP[row * PSTR + kc + tig]);
        qf[ks][1] = __float_as_uint(sP[(row + 8) * PSTR + kc + tig]);
        qf[ks][2] = __float_as_uint(sP[row * PSTR + kc + tig + 4]);
        qf[ks][3] = __float_as_uint(sP[(row + 8) * PSTR + kc + tig + 4]);
    }

    float oa[8][4];
    #pragma unroll
    for (int nt = 0; nt < 8; nt++)
        #pragma unroll
        for (int r = 0; r < 4; r++) oa[nt][r] = 0.f;
    float m0 = -1e30f, m1 = -1e30f, l0 = 0.f, l1 = 0.f;

    for (int kb = 0; kb <= qb; kb++) {
        const float* v = (kb & 1) ? sV1 : sV0;

        // S = Q K^T from sK
        float s[8][4];
        #pragma unroll
        for (int nt = 0; nt < 8; nt++)
            #pragma unroll
            for (int r = 0; r < 4; r++) s[nt][r] = 0.f;
        #pragma unroll
        for (int ks = 0; ks < 8; ks++) {
            int kc = ks * 8;
            #pragma unroll
            for (int nt = 0; nt < 8; nt++) {
                int cn = nt * 8 + g;
                uint32_t b0 = __float_as_uint(sK[cn * KSTR + kc + tig]);
                uint32_t b1 = __float_as_uint(sK[cn * KSTR + kc + tig + 4]);
                mma_tf32(s[nt], qf[ks][0], qf[ks][1], qf[ks][2], qf[ks][3],
                         b0, b1);
            }
        }

        // sK is dead now; prefetch K(kb+1) and V(kb+1) overlapping the rest
        __syncthreads();
        if (kb < qb) {
            uint32_t aVn = ((kb + 1) & 1) ? aV1 : aV0;
            #pragma unroll
            for (int i = 0; i < 8; i++) {
                int idx = t + i * 128;
                int r = idx >> 4, c4 = (idx & 15) << 2;
                size_t goff = base + (size_t)((kb + 1) * 64 + r) * DM + c4;
                cp_async16(aK + (uint32_t)(r * KSTR + c4) * 4u, K + goff);
                cp_async16(aVn + (uint32_t)(r * VSTR + c4) * 4u, V + goff);
            }
            asm volatile("cp.async.commit_group;\n");
        }

        // scale + causal mask (diagonal tile only)
        #pragma unroll
        for (int nt = 0; nt < 8; nt++)
            #pragma unroll
            for (int r = 0; r < 4; r++) s[nt][r] *= 0.125f;
        if (kb == qb) {
            int q0 = row, q1 = row + 8;
            #pragma unroll
            for (int nt = 0; nt < 8; nt++) {
                int c0 = nt * 8 + 2 * tig, c1 = c0 + 1;
                if (c0 > q0) s[nt][0] = -1e30f;
                if (c1 > q0) s[nt][1] = -1e30f;
                if (c0 > q1) s[nt][2] = -1e30f;
                if (c1 > q1) s[nt][3] = -1e30f;
            }
        }

        // online softmax
        float mt0 = -1e30f, mt1 = -1e30f;
        #pragma unroll
        for (int nt = 0; nt < 8; nt++) {
            mt0 = fmaxf(mt0, fmaxf(s[nt][0], s[nt][1]));
            mt1 = fmaxf(mt1, fmaxf(s[nt][2], s[nt][3]));
        }
        #pragma unroll
        for (int o = 1; o <= 2; o <<= 1) {
            mt0 = fmaxf(mt0, __shfl_xor_sync(0xffffffffu, mt0, o));
            mt1 = fmaxf(mt1, __shfl_xor_sync(0xffffffffu, mt1, o));
        }
        float mn0 = fmaxf(m0, mt0), mn1 = fmaxf(m1, mt1);
        float corr0 = __expf(m0 - mn0), corr1 = __expf(m1 - mn1);
        m0 = mn0; m1 = mn1;
        float rs0 = 0.f, rs1 = 0.f;
        #pragma unroll
        for (int nt = 0; nt < 8; nt++) {
            s[nt][0] = __expf(s[nt][0] - mn0);
            s[nt][1] = __expf(s[nt][1] - mn0);
            s[nt][2] = __expf(s[nt][2] - mn1);
            s[nt][3] = __expf(s[nt][3] - mn1);
            rs0 += s[nt][0] + s[nt][1];
            rs1 += s[nt][2] + s[nt][3];
        }
        #pragma unroll
        for (int o = 1; o <= 2; o <<= 1) {
            rs0 += __shfl_xor_sync(0xffffffffu, rs0, o);
            rs1 += __shfl_xor_sync(0xffffffffu, rs1, o);
        }
        l0 = l0 * corr0 + rs0;
        l1 = l1 * corr1 + rs1;
        #pragma unroll
        for (int nt = 0; nt < 8; nt++) {
            oa[nt][0] *= corr0; oa[nt][1] *= corr0;
            oa[nt][2] *= corr1; oa[nt][3] *= corr1;
        }

        // stage P (per-warp private rows)
        #pragma unroll
        for (int nt = 0; nt < 8; nt++) {
            int cc = nt * 8 + 2 * tig;
            *(float2*)&sP[row * PSTR + cc]       = make_float2(s[nt][0], s[nt][1]);
            *(float2*)&sP[(row + 8) * PSTR + cc] = make_float2(s[nt][2], s[nt][3]);
        }
        __syncwarp();

        // O += P @ V   (V row-major: B[k=key][n=d] at v[key*VSTR + d])
        #pragma unroll
        for (int ks = 0; ks < 8; ks++) {
            int kc = ks * 8;
            uint32_t a0 = __float_as_uint(sP[row * PSTR + kc + tig]);
            uint32_t a1 = __float_as_uint(sP[(row + 8) * PSTR + kc + tig]);
            uint32_t a2 = __float_as_uint(sP[row * PSTR + kc + tig + 4]);
            uint32_t a3 = __float_as_uint(sP[(row + 8) * PSTR + kc + tig + 4]);
            #pragma unroll
            for (int nt = 0; nt < 8; nt++) {
                int cn = nt * 8 + g;
                uint32_t b0 = __float_as_uint(v[(kc + tig) * VSTR + cn]);
                uint32_t b1 = __float_as_uint(v[(kc + tig + 4) * VSTR + cn]);
                mma_tf32(oa[nt], a0, a1, a2, a3, b0, b1);
            }
        }

        if (kb < qb) { asm volatile("cp.async.wait_group 0;\n"); }
        __syncthreads();   // async data visible; all warps done with v + sP
    }

    // epilogue (rounded: att feeds the Wo GEMM as an mma operand)
    float inv0 = 1.0f / l0, inv1 = 1.0f / l1;
    size_t r0 = base + (size_t)(qb * 64 + row) * DM;
    size_t r1 = base + (size_t)(qb * 64 + row + 8) * DM;
    #pragma unroll
    for (int nt = 0; nt < 8; nt++) {
        int cc = nt * 8 + 2 * tig;
        *(float2*)(O + r0 + cc) = make_float2(roundtf(oa[nt][0] * inv0),
                                              roundtf(oa[nt][1] * inv0));
        *(float2*)(O + r1 + cc) = make_float2(roundtf(oa[nt][2] * inv1),
                                              roundtf(oa[nt][3] * inv1));
    }
}

// ---------------- launch ----------------
extern "C" void kernel_launch(void* const* d_in, const int* in_sizes, int n_in,
                              void* d_out, int out_size) {
    const float* H    = (const float*)d_in[0];
    const float* Wq   = (const float*)d_in[1];
    const float* Wk   = (const float*)d_in[2];
    const float* Wv   = (const float*)d_in[3];
    const float* Wo   = (const float*)d_in[4];
    const float* ln1g = (const float*)d_in[5];
    const float* ln1b = (const float*)d_in[6];
    const float* ln2g = (const float*)d_in[7];
    const float* ln2b = (const float*)d_in[8];
    const float* W1   = (const float*)d_in[9];
    const float* b1   = (const float*)d_in[10];
    const float* W2   = (const float*)d_in[11];
    const float* b2   = (const float*)d_in[12];
    float* out = (float*)d_out;

    float *xn, *q, *k, *v, *att, *h1, *mlp, *wqkvo, *w1r, *w2r;
    cudaGetSymbolAddress((void**)&xn,    g_xn);
    cudaGetSymbolAddress((void**)&q,     g_q);
    cudaGetSymbolAddress((void**)&k,     g_k);
    cudaGetSymbolAddress((void**)&v,     g_v);
    cudaGetSymbolAddress((void**)&att,   g_att);
    cudaGetSymbolAddress((void**)&h1,    g_h1);
    cudaGetSymbolAddress((void**)&mlp,   g_mlp);
    cudaGetSymbolAddress((void**)&wqkvo, g_wqkvo);
    cudaGetSymbolAddress((void**)&w1r,   g_w1r);
    cudaGetSymbolAddress((void**)&w2r,   g_w2r);

    cudaFuncSetAttribute(attn_tc, cudaFuncAttributeMaxDynamicSharedMemorySize,
                         ATTN_SMEM);
    cudaFuncSetAttribute(gemm_qkv, cudaFuncAttributeMaxDynamicSharedMemorySize,
                         (int)GEMM_SMEM);
    cudaFuncSetAttribute(gemm_tf32<1, 1>, cudaFuncAttributeMaxDynamicSharedMemorySize,
                         (int)GEMM_SMEM);
    cudaFuncSetAttribute(gemm_tf32<2, 0>, cudaFuncAttributeMaxDynamicSharedMemorySize,
                         (int)GEMM_SMEM);
    cudaFuncSetAttribute(gemm_tf32<3, 0>, cudaFuncAttributeMaxDynamicSharedMemorySize,
                         (int)GEMM_SMEM);

    dim3 gProj(DM / 128, TOK / 128);        // 8 x 32
    dim3 gQkv(DM / 128, TOK / 128, 3);      // 8 x 32 x 3
    dim3 gMlp1(DFF / 128, TOK / 128);       // 32 x 32

    // pre-round all weights to tf32 (single fused launch; graph-captured)
    int n4p = DM * DM / 4;                  // 262144
    int n4f = DM * DFF / 4;                 // 1048576
    RoundArgs ra;
    ra.src[0] = (const float4*)Wq; ra.dst[0] = (float4*)wqkvo;                 ra.n4[0] = n4p;
    ra.src[1] = (const float4*)Wk; ra.dst[1] = (float4*)(wqkvo + DM * DM);     ra.n4[1] = n4p;
    ra.src[2] = (const float4*)Wv; ra.dst[2] = (float4*)(wqkvo + 2 * DM * DM); ra.n4[2] = n4p;
    ra.src[3] = (const float4*)Wo; ra.dst[3] = (float4*)(wqkvo + 3 * DM * DM); ra.n4[3] = n4p;
    ra.src[4] = (const float4*)W1; ra.dst[4] = (float4*)w1r;                   ra.n4[4] = n4f;
    ra.src[5] = (const float4*)W2; ra.dst[5] = (float4*)w2r;                   ra.n4[5] = n4f;
    round_all<<<dim3((n4f + 255) / 256, 6), 256>>>(ra);

    // LN1
    ln_kernel<<<TOK, 256>>>(H, ln1g, ln1b, xn);
    // fused Q, K, V projections
    gemm_qkv<<<gQkv, 256, GEMM_SMEM>>>(xn, wqkvo, q, k, v, TOK, DM, DM);
    // fused causal attention (tensor cores, async-pipelined K/V)
    attn_tc<<<dim3(32, 16, 2), 128, ATTN_SMEM>>>(q, k, v, att);
    // O projection + residual (exact fp32 residual stream)
    gemm_tf32<3, 0><<<gProj, 256, GEMM_SMEM>>>(att, wqkvo + 3 * DM * DM, nullptr, H,
                                               h1, TOK, DM, DM);
    // LN2
    ln_kernel<<<TOK, 256>>>(h1, ln2g, ln2b, xn);
    // MLP
    gemm_tf32<1, 1><<<gMlp1, 256, GEMM_SMEM>>>(xn, w1r, b1, nullptr, mlp, TOK, DFF, DM);
    gemm_tf32<2, 0><<<gProj, 256, GEMM_SMEM>>>(mlp, w2r, b2, h1, out, TOK, DM, DFF);
}

// round 9
// speedup vs baseline: 2.0185x; 1.8866x over previous
#include <cuda_runtime.h>
#include <cuda_fp16.h>
#include <stdint.h>
#include <math.h>

#define TOK 4096
#define DM 1024
#define DFF 4096

// ---------------- scratch (static device globals; no allocs) ----------------
__device__ __half g_xn[TOK * DM];            // LN output (fp16)
__device__ __half g_q[TOK * DM];
__device__ __half g_k[TOK * DM];
__device__ __half g_v[TOK * DM];
__device__ __half g_att[TOK * DM];
__device__ float  g_h1[TOK * DM];            // residual stream (exact fp32)
__device__ __half g_mlp[(size_t)TOK * DFF];  // GELU hidden (fp16)
__device__ __half g_wqkvoT[4 * DM * DM];     // transposed fp16 weights [N][K]
__device__ __half g_w1T[(size_t)DFF * DM];   // [4096][1024]
__device__ __half g_w2T[(size_t)DM * DFF];   // [1024][4096]

// ---------------- FP16 mma primitive ----------------
__device__ __forceinline__ void mma_f16(float c[4],
                                        uint32_t a0, uint32_t a1,
                                        uint32_t a2, uint32_t a3,
                                        uint32_t b0, uint32_t b1) {
    asm volatile(
        "mma.sync.aligned.m16n8k16.row.col.f32.f16.f16.f32 "
        "{%0,%1,%2,%3}, {%4,%5,%6,%7}, {%8,%9}, {%0,%1,%2,%3};\n"
        : "+f"(c[0]), "+f"(c[1]), "+f"(c[2]), "+f"(c[3])
        : "r"(a0), "r"(a1), "r"(a2), "r"(a3), "r"(b0), "r"(b1));
}

__device__ __forceinline__ void cp_async16(uint32_t smem, const void* gptr) {
    asm volatile("cp.async.cg.shared.global [%0], [%1], 16;\n"
                 :: "r"(smem), "l"(gptr));
}

__device__ __forceinline__ uint32_t ld32h(const __half* p) {
    return *reinterpret_cast<const uint32_t*>(p);
}

// ---------------- transpose + fp32->fp16 convert: dst[C][R] = src[R][C] ----
__global__ __launch_bounds__(256) void transpose_h(const float* __restrict__ src,
                                                   __half* __restrict__ dst,
                                                   int R, int C) {
    __shared__ __half tile[32][33];
    int c0 = blockIdx.x * 32, r0 = blockIdx.y * 32;
    int tx = threadIdx.x, ty = threadIdx.y;          // 32 x 8
    #pragma unroll
    for (int i = ty; i < 32; i += 8)
        tile[i][tx] = __float2half_rn(src[(size_t)(r0 + i) * C + c0 + tx]);
    __syncthreads();
    #pragma unroll
    for (int i = ty; i < 32; i += 8)
        dst[(size_t)(c0 + i) * R + r0 + tx] = tile[tx][i];
}

// ---------------- LayerNorm: fp32 in, fp16 out ----------------
__global__ __launch_bounds__(256) void ln_kernel(const float* __restrict__ x,
                                                 const float* __restrict__ g,
                                                 const float* __restrict__ b,
                                                 __half* __restrict__ out) {
    int row = blockIdx.x;
    int t = threadIdx.x;
    const float4* xr = (const float4*)(x + (size_t)row * DM);
    float4 v = xr[t];
    float s  = v.x + v.y + v.z + v.w;
    float ss = v.x * v.x + v.y * v.y + v.z * v.z + v.w * v.w;
    #pragma unroll
    for (int o = 16; o > 0; o >>= 1) {
        s  += __shfl_xor_sync(0xffffffffu, s, o);
        ss += __shfl_xor_sync(0xffffffffu, ss, o);
    }
    __shared__ float red[2][8];
    if ((t & 31) == 0) { red[0][t >> 5] = s; red[1][t >> 5] = ss; }
    __syncthreads();
    float ts = 0.f, tss = 0.f;
    #pragma unroll
    for (int i = 0; i < 8; i++) { ts += red[0][i]; tss += red[1][i]; }
    float mu   = ts * (1.0f / DM);
    float var  = tss * (1.0f / DM) - mu * mu;
    float rstd = rsqrtf(var + 1e-5f);
    float4 gv = ((const float4*)g)[t];
    float4 bv = ((const float4*)b)[t];
    __half2 h01 = __floats2half2_rn((v.x - mu) * rstd * gv.x + bv.x,
                                    (v.y - mu) * rstd * gv.y + bv.y);
    __half2 h23 = __floats2half2_rn((v.z - mu) * rstd * gv.z + bv.z,
                                    (v.w - mu) * rstd * gv.w + bv.w);
    uint2 st;
    st.x = *reinterpret_cast<uint32_t*>(&h01);
    st.y = *reinterpret_cast<uint32_t*>(&h23);
    *(uint2*)(out + (size_t)row * DM + t * 4) = st;
}

// ---------------- FP16 tensor-core GEMM ----------------
// C[M,N] = A[M,K] @ Bt[N,K]^T (+ epilogue). A, Bt fp16; accum fp32.
// EPI: 0 = none, 1 = +bias exact GELU, 2 = +bias +res, 3 = +res
// Block tile 128x128x64, 8 warps 2(m) x 4(n); per warp 4x4 m16n8k16 tiles.
// Smem stride 72 halves -> fragment-load bank = 4g+tig, conflict-free.

#define HSTR 72
#define TILEB (128 * HSTR * 2)      // 18432 B per tile
#define BUFB  (2 * TILEB)           // 36864 B per buffer (A+B)
#define GEMM_SMEM (2 * BUFB)        // 73728 B

template <int EPI, typename OT>
__device__ __forceinline__ void gemm_body(const __half* __restrict__ A,
                                          const __half* __restrict__ Bt,
                                          const float* __restrict__ bias,
                                          const float* __restrict__ res,
                                          OT* __restrict__ C,
                                          int M, int N, int K, char* smc) {
    uint32_t sbase = (uint32_t)__cvta_generic_to_shared(smc);

    int t = threadIdx.x;
    int bn = blockIdx.x, bm = blockIdx.y;
    int wid = t >> 5, lane = t & 31;
    int wm = wid & 1, wn = wid >> 1;          // 2 x 4 warp grid
    int g = lane >> 2, tig = lane & 3;

    auto load_tiles = [&](int k0, int buf) {
        uint32_t sa = sbase + (uint32_t)buf * BUFB;
        uint32_t sb = sa + TILEB;
        #pragma unroll
        for (int i = 0; i < 4; i++) {          // 128 rows x 64 halves (8x16B)
            int idx = t + i * 256;
            int r = idx >> 3, c = (idx & 7) * 8;
            cp_async16(sa + (uint32_t)(r * HSTR + c) * 2u,
                       A + (size_t)(bm * 128 + r) * K + k0 + c);
            cp_async16(sb + (uint32_t)(r * HSTR + c) * 2u,
                       Bt + (size_t)(bn * 128 + r) * K + k0 + c);
        }
        asm volatile("cp.async.commit_group;\n");
    };

    float acc[4][4][4];
    #pragma unroll
    for (int i = 0; i < 4; i++)
        #pragma unroll
        for (int j = 0; j < 4; j++)
            #pragma unroll
            for (int r = 0; r < 4; r++) acc[i][j][r] = 0.f;

    load_tiles(0, 0);
    int NC = K >> 6;
    for (int c = 0; c < NC; c++) {
        asm volatile("cp.async.wait_group 0;\n");
        __syncthreads();
        if (c + 1 < NC) load_tiles((c + 1) << 6, (c + 1) & 1);

        const __half* a = (const __half*)(smc + (c & 1) * BUFB);
        const __half* b = (const __half*)(smc + (c & 1) * BUFB + TILEB);

        #pragma unroll
        for (int ks = 0; ks < 4; ks++) {
            int kc = ks * 16;
            uint32_t af[4][4], bf[4][2];
            #pragma unroll
            for (int mt = 0; mt < 4; mt++) {
                int r = wm * 64 + mt * 16 + g;
                af[mt][0] = ld32h(&a[r * HSTR + kc + 2 * tig]);
                af[mt][1] = ld32h(&a[(r + 8) * HSTR + kc + 2 * tig]);
                af[mt][2] = ld32h(&a[r * HSTR + kc + 2 * tig + 8]);
                af[mt][3] = ld32h(&a[(r + 8) * HSTR + kc + 2 * tig + 8]);
            }
            #pragma unroll
            for (int nt = 0; nt < 4; nt++) {
                int cn = wn * 32 + nt * 8 + g;
                bf[nt][0] = ld32h(&b[cn * HSTR + kc + 2 * tig]);
                bf[nt][1] = ld32h(&b[cn * HSTR + kc + 2 * tig + 8]);
            }
            #pragma unroll
            for (int mt = 0; mt < 4; mt++)
                #pragma unroll
                for (int nt = 0; nt < 4; nt++)
                    mma_f16(acc[mt][nt], af[mt][0], af[mt][1], af[mt][2],
                            af[mt][3], bf[nt][0], bf[nt][1]);
        }
        __syncthreads();
    }

    int row0 = bm * 128 + wm * 64;
    int col0 = bn * 128 + wn * 32;
    #pragma unroll
    for (int mt = 0; mt < 4; mt++) {
        #pragma unroll
        for (int half_ = 0; half_ < 2; half_++) {
            int r = row0 + mt * 16 + half_ * 8 + g;
            size_t rb = (size_t)r * N;
            #pragma unroll
            for (int nt = 0; nt < 4; nt++) {
                int cn = col0 + nt * 8 + tig * 2;
                float x0 = acc[mt][nt][half_ * 2];
                float x1 = acc[mt][nt][half_ * 2 + 1];
                if (EPI == 1) {
                    x0 += bias[cn];
                    x1 += bias[cn + 1];
                    x0 = 0.5f * x0 * (1.0f + erff(x0 * 0.70710678118654752f));
                    x1 = 0.5f * x1 * (1.0f + erff(x1 * 0.70710678118654752f));
                } else if (EPI == 2) {
                    x0 += bias[cn] + res[rb + cn];
                    x1 += bias[cn + 1] + res[rb + cn + 1];
                } else if (EPI == 3) {
                    x0 += res[rb + cn];
                    x1 += res[rb + cn + 1];
                }
                if (sizeof(OT) == 2) {
                    __half2 h = __floats2half2_rn(x0, x1);
                    *(uint32_t*)((__half*)C + rb + cn) =
                        *reinterpret_cast<uint32_t*>(&h);
                } else {
                    *(float2*)((float*)C + rb + cn) = make_float2(x0, x1);
                }
            }
        }
    }
}

template <int EPI, typename OT>
__global__ __launch_bounds__(256) void gemm_f16(const __half* __restrict__ A,
                                                const __half* __restrict__ Bt,
                                                const float* __restrict__ bias,
                                                const float* __restrict__ res,
                                                OT* __restrict__ C,
                                                int M, int N, int K) {
    extern __shared__ char smc[];
    gemm_body<EPI, OT>(A, Bt, bias, res, C, M, N, K, smc);
}

// Fused Q/K/V projection: blockIdx.z selects weight + destination.
__global__ __launch_bounds__(256) void gemm_qkv(const __half* __restrict__ A,
                                                const __half* __restrict__ Wt,
                                                __half* __restrict__ q,
                                                __half* __restrict__ k,
                                                __half* __restrict__ v,
                                                int M, int N, int K) {
    extern __shared__ char smc[];
    const __half* Bt = Wt + (size_t)blockIdx.z * DM * DM;
    __half* C = (blockIdx.z == 0) ? q : (blockIdx.z == 1) ? k : v;
    gemm_body<0, __half>(A, Bt, nullptr, nullptr, C, M, N, K, smc);
}

// ---------------- FP16 tensor-core causal flash attention ----------------
// Q,K,V fp16. K tile natural [key][d] serves QK^T b-frags as contiguous pairs.
// V row-major; PV b-frags via paired u16 loads. K/V(kb+1) prefetched via
// cp.async overlapping softmax+PV. P staged as half2 (per-warp rows).
#define AKSTR 72
#define AVSTR 72
#define APSTR 72
#define ATILE (64 * 72)                        // halves per tile
#define ATTN_SMEM (4 * ATILE * 2)              // K + 2V + P = 36864 B

__global__ __launch_bounds__(128) void attn_tc(const __half* __restrict__ Q,
                                               const __half* __restrict__ K,
                                               const __half* __restrict__ V,
                                               __half* __restrict__ O) {
    extern __shared__ char smc[];
    __half* sK  = (__half*)smc;                // [64][72]
    __half* sV0 = sK + ATILE;
    __half* sV1 = sV0 + ATILE;
    __half* sP  = sV1 + ATILE;                 // Q staging, then per-warp P
    uint32_t sbase = (uint32_t)__cvta_generic_to_shared(smc);
    uint32_t aK  = sbase;
    uint32_t aV0 = aK + ATILE * 2;
    uint32_t aV1 = aV0 + ATILE * 2;
    uint32_t aP  = aV1 + ATILE * 2;

    int qb = gridDim.x - 1 - blockIdx.x;       // big tiles first
    int h = blockIdx.y, bb = blockIdx.z;
    int t = threadIdx.x;
    int w = t >> 5, lane = t & 31;
    int g = lane >> 2, tig = lane & 3;
    int row = w * 16 + g;
    size_t base = ((size_t)bb * 2048) * DM + (size_t)h * 64;

    // prologue: Q -> sP, K(0) -> sK, V(0) -> sV0 (64 rows x 64 halves each)
    #pragma unroll
    for (int i = 0; i < 4; i++) {
        int idx = t + i * 128;
        int r = idx >> 3, c = (idx & 7) * 8;
        cp_async16(aP + (uint32_t)(r * APSTR + c) * 2u,
                   Q + base + (size_t)(qb * 64 + r) * DM + c);
        size_t goff = base + (size_t)r * DM + c;
        cp_async16(aK + (uint32_t)(r * AKSTR + c) * 2u, K + goff);
        cp_async16(aV0 + (uint32_t)(r * AVSTR + c) * 2u, V + goff);
    }
    asm volatile("cp.async.commit_group;\n");
    asm volatile("cp.async.wait_group 0;\n");
    __syncthreads();

    // Q fragments in registers for the whole kernel (4 k-steps of 16)
    uint32_t qf[4][4];
    #pragma unroll
    for (int ks = 0; ks < 4; ks++) {
        int kc = ks * 16;
        qf[ks][0] = ld32h(&sP[row * APSTR + kc + 2 * tig]);
        qf[ks][1] = ld32h(&sP[(row + 8) * APSTR + kc + 2 * tig]);
        qf[ks][2] = ld32h(&sP[row * APSTR + kc + 2 * tig + 8]);
        qf[ks][3] = ld32h(&sP[(row + 8) * APSTR + kc + 2 * tig + 8]);
    }

    float oa[8][4];
    #pragma unroll
    for (int nt = 0; nt < 8; nt++)
        #pragma unroll
        for (int r = 0; r < 4; r++) oa[nt][r] = 0.f;
    float m0 = -1e30f, m1 = -1e30f, l0 = 0.f, l1 = 0.f;

    for (int kb = 0; kb <= qb; kb++) {
        const __half* v = (kb & 1) ? sV1 : sV0;

        // S = Q K^T
        float s[8][4];
        #pragma unroll
        for (int nt = 0; nt < 8; nt++)
            #pragma unroll
            for (int r = 0; r < 4; r++) s[nt][r] = 0.f;
        #pragma unroll
        for (int ks = 0; ks < 4; ks++) {
            int kc = ks * 16;
            #pragma unroll
            for (int nt = 0; nt < 8; nt++) {
                int cn = nt * 8 + g;
                uint32_t b0 = ld32h(&sK[cn * AKSTR + kc + 2 * tig]);
                uint32_t b1 = ld32h(&sK[cn * AKSTR + kc + 2 * tig + 8]);
                mma_f16(s[nt], qf[ks][0], qf[ks][1], qf[ks][2], qf[ks][3],
                        b0, b1);
            }
        }

        // sK dead: prefetch K(kb+1), V(kb+1) overlapping the rest
        __syncthreads();
        if (kb < qb) {
            uint32_t aVn = ((kb + 1) & 1) ? aV1 : aV0;
            #pragma unroll
            for (int i = 0; i < 4; i++) {
                int idx = t + i * 128;
                int r = idx >> 3, c = (idx & 7) * 8;
                size_t goff = base + (size_t)((kb + 1) * 64 + r) * DM + c;
                cp_async16(aK + (uint32_t)(r * AKSTR + c) * 2u, K + goff);
                cp_async16(aVn + (uint32_t)(r * AVSTR + c) * 2u, V + goff);
            }
            asm volatile("cp.async.commit_group;\n");
        }

        // scale + causal mask
        #pragma unroll
        for (int nt = 0; nt < 8; nt++)
            #pragma unroll
            for (int r = 0; r < 4; r++) s[nt][r] *= 0.125f;
        if (kb == qb) {
            int q0 = row, q1 = row + 8;
            #pragma unroll
            for (int nt = 0; nt < 8; nt++) {
                int c0 = nt * 8 + 2 * tig, c1 = c0 + 1;
                if (c0 > q0) s[nt][0] = -1e30f;
                if (c1 > q0) s[nt][1] = -1e30f;
                if (c0 > q1) s[nt][2] = -1e30f;
                if (c1 > q1) s[nt][3] = -1e30f;
            }
        }

        // online softmax
        float mt0 = -1e30f, mt1 = -1e30f;
        #pragma unroll
        for (int nt = 0; nt < 8; nt++) {
            mt0 = fmaxf(mt0, fmaxf(s[nt][0], s[nt][1]));
            mt1 = fmaxf(mt1, fmaxf(s[nt][2], s[nt][3]));
        }
        #pragma unroll
        for (int o = 1; o <= 2; o <<= 1) {
            mt0 = fmaxf(mt0, __shfl_xor_sync(0xffffffffu, mt0, o));
            mt1 = fmaxf(mt1, __shfl_xor_sync(0xffffffffu, mt1, o));
        }
        float mn0 = fmaxf(m0, mt0), mn1 = fmaxf(m1, mt1);
        float corr0 = __expf(m0 - mn0), corr1 = __expf(m1 - mn1);
        m0 = mn0; m1 = mn1;
        float rs0 = 0.f, rs1 = 0.f;
        #pragma unroll
        for (int nt = 0; nt < 8; nt++) {
            s[nt][0] = __expf(s[nt][0] - mn0);
            s[nt][1] = __expf(s[nt][1] - mn0);
            s[nt][2] = __expf(s[nt][2] - mn1);
            s[nt][3] = __expf(s[nt][3] - mn1);
            rs0 += s[nt][0] + s[nt][1];
            rs1 += s[nt][2] + s[nt][3];
        }
        #pragma unroll
        for (int o = 1; o <= 2; o <<= 1) {
            rs0 += __shfl_xor_sync(0xffffffffu, rs0, o);
            rs1 += __shfl_xor_sync(0xffffffffu, rs1, o);
        }
        l0 = l0 * corr0 + rs0;
        l1 = l1 * corr1 + rs1;
        #pragma unroll
        for (int nt = 0; nt < 8; nt++) {
            oa[nt][0] *= corr0; oa[nt][1] *= corr0;
            oa[nt][2] *= corr1; oa[nt][3] *= corr1;
        }

        // stage P as half2 (per-warp private rows)
        #pragma unroll
        for (int nt = 0; nt < 8; nt++) {
            int cc = nt * 8 + 2 * tig;
            __half2 p0 = __floats2half2_rn(s[nt][0], s[nt][1]);
            __half2 p1 = __floats2half2_rn(s[nt][2], s[nt][3]);
            *(uint32_t*)&sP[row * APSTR + cc] = *reinterpret_cast<uint32_t*>(&p0);
            *(uint32_t*)&sP[(row + 8) * APSTR + cc] = *reinterpret_cast<uint32_t*>(&p1);
        }
        __syncwarp();

        // O += P @ V   (V row-major; b-frag pairs along key via u16 loads)
        #pragma unroll
        for (int ks = 0; ks < 4; ks++) {
            int kc = ks * 16;
            uint32_t a0 = ld32h(&sP[row * APSTR + kc + 2 * tig]);
            uint32_t a1 = ld32h(&sP[(row + 8) * APSTR + kc + 2 * tig]);
            uint32_t a2 = ld32h(&sP[row * APSTR + kc + 2 * tig + 8]);
            uint32_t a3 = ld32h(&sP[(row + 8) * APSTR + kc + 2 * tig + 8]);
            #pragma unroll
            for (int nt = 0; nt < 8; nt++) {
                int cn = nt * 8 + g;
                int k0 = kc + 2 * tig;
                uint32_t b0 =
                    (uint32_t)*(const unsigned short*)&v[k0 * AVSTR + cn] |
                    ((uint32_t)*(const unsigned short*)&v[(k0 + 1) * AVSTR + cn] << 16);
                uint32_t b1 =
                    (uint32_t)*(const unsigned short*)&v[(k0 + 8) * AVSTR + cn] |
                    ((uint32_t)*(const unsigned short*)&v[(k0 + 9) * AVSTR + cn] << 16);
                mma_f16(oa[nt], a0, a1, a2, a3, b0, b1);
            }
        }

        if (kb < qb) { asm volatile("cp.async.wait_group 0;\n"); }
        __syncthreads();
    }

    // epilogue: normalize, store fp16
    float inv0 = 1.0f / l0, inv1 = 1.0f / l1;
    size_t r0 = base + (size_t)(qb * 64 + row) * DM;
    size_t r1 = base + (size_t)(qb * 64 + row + 8) * DM;
    #pragma unroll
    for (int nt = 0; nt < 8; nt++) {
        int cc = nt * 8 + 2 * tig;
        __half2 o0 = __floats2half2_rn(oa[nt][0] * inv0, oa[nt][1] * inv0);
        __half2 o1 = __floats2half2_rn(oa[nt][2] * inv1, oa[nt][3] * inv1);
        *(uint32_t*)(O + r0 + cc) = *reinterpret_cast<uint32_t*>(&o0);
        *(uint32_t*)(O + r1 + cc) = *reinterpret_cast<uint32_t*>(&o1);
    }
}

// ---------------- launch ----------------
extern "C" void kernel_launch(void* const* d_in, const int* in_sizes, int n_in,
                              void* d_out, int out_size) {
    const float* H    = (const float*)d_in[0];
    const float* Wq   = (const float*)d_in[1];
    const float* Wk   = (const float*)d_in[2];
    const float* Wv   = (const float*)d_in[3];
    const float* Wo   = (const float*)d_in[4];
    const float* ln1g = (const float*)d_in[5];
    const float* ln1b = (const float*)d_in[6];
    const float* ln2g = (const float*)d_in[7];
    const float* ln2b = (const float*)d_in[8];
    const float* W1   = (const float*)d_in[9];
    const float* b1   = (const float*)d_in[10];
    const float* W2   = (const float*)d_in[11];
    const float* b2   = (const float*)d_in[12];
    float* out = (float*)d_out;

    __half *xn, *q, *k, *v, *att, *mlp, *wqkvoT, *w1T, *w2T;
    float *h1;
    cudaGetSymbolAddress((void**)&xn,     g_xn);
    cudaGetSymbolAddress((void**)&q,      g_q);
    cudaGetSymbolAddress((void**)&k,      g_k);
    cudaGetSymbolAddress((void**)&v,      g_v);
    cudaGetSymbolAddress((void**)&att,    g_att);
    cudaGetSymbolAddress((void**)&h1,     g_h1);
    cudaGetSymbolAddress((void**)&mlp,    g_mlp);
    cudaGetSymbolAddress((void**)&wqkvoT, g_wqkvoT);
    cudaGetSymbolAddress((void**)&w1T,    g_w1T);
    cudaGetSymbolAddress((void**)&w2T,    g_w2T);

    cudaFuncSetAttribute(attn_tc, cudaFuncAttributeMaxDynamicSharedMemorySize,
                         ATTN_SMEM);
    cudaFuncSetAttribute(gemm_qkv, cudaFuncAttributeMaxDynamicSharedMemorySize,
                         (int)GEMM_SMEM);
    cudaFuncSetAttribute((const void*)gemm_f16<1, __half>,
                         cudaFuncAttributeMaxDynamicSharedMemorySize, (int)GEMM_SMEM);
    cudaFuncSetAttribute((const void*)gemm_f16<2, float>,
                         cudaFuncAttributeMaxDynamicSharedMemorySize, (int)GEMM_SMEM);
    cudaFuncSetAttribute((const void*)gemm_f16<3, float>,
                         cudaFuncAttributeMaxDynamicSharedMemorySize, (int)GEMM_SMEM);

    dim3 gProj(DM / 128, TOK / 128);        // 8 x 32
    dim3 gQkv(DM / 128, TOK / 128, 3);      // 8 x 32 x 3
    dim3 gMlp1(DFF / 128, TOK / 128);       // 32 x 32
    dim3 tb(32, 8);

    // transpose + convert weights to fp16 [N][K] (graph-captured, once/launch)
    transpose_h<<<dim3(DM / 32, DM / 32), tb>>>(Wq, wqkvoT, DM, DM);
    transpose_h<<<dim3(DM / 32, DM / 32), tb>>>(Wk, wqkvoT + DM * DM, DM, DM);
    transpose_h<<<dim3(DM / 32, DM / 32), tb>>>(Wv, wqkvoT + 2 * DM * DM, DM, DM);
    transpose_h<<<dim3(DM / 32, DM / 32), tb>>>(Wo, wqkvoT + 3 * DM * DM, DM, DM);
    transpose_h<<<dim3(DFF / 32, DM / 32), tb>>>(W1, w1T, DM, DFF);
    transpose_h<<<dim3(DM / 32, DFF / 32), tb>>>(W2, w2T, DFF, DM);

    // LN1
    ln_kernel<<<TOK, 256>>>(H, ln1g, ln1b, xn);
    // fused Q, K, V projections
    gemm_qkv<<<gQkv, 256, GEMM_SMEM>>>(xn, wqkvoT, q, k, v, TOK, DM, DM);
    // fused causal attention
    attn_tc<<<dim3(32, 16, 2), 128, ATTN_SMEM>>>(q, k, v, att);
    // O projection + residual (fp32 residual stream)
    gemm_f16<3, float><<<gProj, 256, GEMM_SMEM>>>(att, wqkvoT + 3 * DM * DM,
                                                  nullptr, H, h1, TOK, DM, DM);
    // LN2
    ln_kernel<<<TOK, 256>>>(h1, ln2g, ln2b, xn);
    // MLP
    gemm_f16<1, __half><<<gMlp1, 256, GEMM_SMEM>>>(xn, w1T, b1, nullptr, mlp,
                                                   TOK, DFF, DM);
    gemm_f16<2, float><<<gProj, 256, GEMM_SMEM>>>(mlp, w2T, b2, h1, out,
                                                  TOK, DM, DFF);
}